// round 12
// baseline (speedup 1.0000x reference)
#include <cuda_runtime.h>

#define NN 50000
#define EE 800000
#define INC 32
#define OUTC 64
#define KPROD 25

// ---------------- device scratch (no allocation allowed) ----------------
__device__ __align__(16) int    g_src[EE];
__device__ __align__(16) int    g_dst[EE];
__device__ __align__(16) float4 g_basis[EE];
__device__ __align__(16) uchar4 g_widx[EE];
__device__ __align__(16) float  g_y[(size_t)NN * KPROD * OUTC];   // 320 MB
__device__ __align__(16) float  g_agg[NN * OUTC];
__device__ __align__(16) float  g_deg[NN];
__device__ __align__(16) float  g_x1[NN * OUTC];
__device__ __align__(16) float  g_x2[NN * OUTC];
__device__ int g_is64;   // 1 if edge_index buffer is true int64, 0 if int32

// ---------------- detect edge_index dtype (runs every replay; deterministic) ----------------
__global__ void detect_kernel(const void* ei) {
    if (threadIdx.x == 0 && blockIdx.x == 0) {
        const long long* p64 = (const long long*)ei;
        int ok64 = 1;
        for (int i = 0; i < 64; i++) {
            long long v = p64[i];
            if (v < 0 || v >= NN) { ok64 = 0; break; }
        }
        g_is64 = ok64;
    }
}

// ---------------- zero agg + deg (start of each replay) ----------------
__global__ void zero_kernel() {
    int i = blockIdx.x * blockDim.x + threadIdx.x;
    if (i < NN * OUTC) g_agg[i] = 0.f;
    if (i < NN)        g_deg[i] = 0.f;
}

// ---------------- per-edge basis / widx / src / dst / deg ----------------
__global__ __launch_bounds__(256) void prep_kernel(const void* __restrict__ ei,
                                                   const float* __restrict__ attr) {
    int e = blockIdx.x * 256 + threadIdx.x;
    if (e >= EE) return;
    int s, d;
    if (g_is64) {
        const long long* p = (const long long*)ei;
        s = (int)p[e];
        d = (int)p[EE + e];
    } else {
        const int* p = (const int*)ei;
        s = p[e];
        d = p[EE + e];
    }
    // defensive clamp: any residual garbage becomes a rel_err signal, not a trap
    s = min(max(s, 0), NN - 1);
    d = min(max(d, 0), NN - 1);
    g_src[e] = s;
    g_dst[e] = d;
    atomicAdd(&g_deg[d], 1.f);

    float v0 = attr[2 * e]     * 4.f;
    float v1 = attr[2 * e + 1] * 4.f;
    float fl0 = floorf(v0), fl1 = floorf(v1);
    int   b0 = (int)fl0,    b1 = (int)fl1;
    float f0 = v0 - fl0,    f1 = v1 - fl1;
    float g0 = 1.f - f0,    g1 = 1.f - f1;

    // s bit order: bit d = (s>>d)&1 ; basis_s = prod_d (bit? frac : 1-frac)
    float4 bas = make_float4(g0 * g1, f0 * g1, g0 * f1, f0 * f1);
    int k00 = min(max(b0, 0), 4), k01 = min(max(b0 + 1, 0), 4);
    int k10 = min(max(b1, 0), 4), k11 = min(max(b1 + 1, 0), 4);
    uchar4 wi;
    wi.x = (unsigned char)(k00 + 5 * k10);
    wi.y = (unsigned char)(k01 + 5 * k10);
    wi.z = (unsigned char)(k00 + 5 * k11);
    wi.w = (unsigned char)(k01 + 5 * k11);
    g_basis[e] = bas;
    g_widx[e]  = wi;
}

// ---------------- 4x4 microtile MAC ----------------
__device__ __forceinline__ void mac16(float acc[4][4], const float* xsrow, const float* wsrow) {
    float4 xv = *(const float4*)xsrow;
    float4 wv = *(const float4*)wsrow;
    acc[0][0] += xv.x * wv.x; acc[0][1] += xv.x * wv.y; acc[0][2] += xv.x * wv.z; acc[0][3] += xv.x * wv.w;
    acc[1][0] += xv.y * wv.x; acc[1][1] += xv.y * wv.y; acc[1][2] += xv.y * wv.z; acc[1][3] += xv.y * wv.w;
    acc[2][0] += xv.z * wv.x; acc[2][1] += xv.z * wv.y; acc[2][2] += xv.z * wv.z; acc[2][3] += xv.z * wv.w;
    acc[3][0] += xv.w * wv.x; acc[3][1] += xv.w * wv.y; acc[3][2] += xv.w * wv.z; acc[3][3] += xv.w * wv.w;
}

// ---------------- y[n,k,:] = x[n,:] @ w[k]  (grid: nodeTiles x KPROD) ----------------
template <int CIN, int LAYER>
__global__ __launch_bounds__(256) void transform_kernel(const float* __restrict__ xin,
                                                        const float* __restrict__ w) {
    __shared__ __align__(16) float xs[CIN][68];
    __shared__ __align__(16) float ws[CIN * 64];
    const float* src = (LAYER == 0) ? xin : g_x1;
    int k  = blockIdx.y;
    int n0 = blockIdx.x * 64;
    int t  = threadIdx.x;

    for (int idx = t; idx < 64 * CIN; idx += 256) {
        int nl = idx / CIN, i = idx % CIN;
        int n = n0 + nl;
        xs[i][nl] = (n < NN) ? src[n * CIN + i] : 0.f;
    }
    for (int idx = t; idx < CIN * 64; idx += 256)
        ws[idx] = w[k * CIN * 64 + idx];
    __syncthreads();

    int tx = t & 15, ty = t >> 4;
    float acc[4][4] = {};
#pragma unroll 8
    for (int i = 0; i < CIN; i++)
        mac16(acc, &xs[i][ty * 4], &ws[i * 64 + tx * 4]);

    int obase = tx * 4;
#pragma unroll
    for (int j = 0; j < 4; j++) {
        int n = n0 + ty * 4 + j;
        if (n < NN) {
            float4 v = make_float4(acc[j][0], acc[j][1], acc[j][2], acc[j][3]);
            *(float4*)&g_y[((size_t)n * KPROD + k) * 64 + obase] = v;
        }
    }
}

// ---------------- per-edge gather of 4 y-rows, scatter-add to agg ----------------
__global__ __launch_bounds__(256) void gather_kernel() {
    int gtid = blockIdx.x * 256 + threadIdx.x;
    int e    = gtid >> 4;          // edge index
    int lane = gtid & 15;          // 16 lanes cover 64 floats as float4
    if (e >= EE) return;
    int src = g_src[e];
    int dst = g_dst[e];
    float4 bas = g_basis[e];
    uchar4 wi  = g_widx[e];
    const float4* __restrict__ base = (const float4*)(g_y + (size_t)src * (KPROD * 64));
    float4 v0 = __ldg(&base[wi.x * 16 + lane]);
    float4 v1 = __ldg(&base[wi.y * 16 + lane]);
    float4 v2 = __ldg(&base[wi.z * 16 + lane]);
    float4 v3 = __ldg(&base[wi.w * 16 + lane]);
    float4 acc;
    acc.x = bas.x * v0.x + bas.y * v1.x + bas.z * v2.x + bas.w * v3.x;
    acc.y = bas.x * v0.y + bas.y * v1.y + bas.z * v2.y + bas.w * v3.y;
    acc.z = bas.x * v0.z + bas.y * v1.z + bas.z * v2.z + bas.w * v3.z;
    acc.w = bas.x * v0.w + bas.y * v1.w + bas.z * v2.w + bas.w * v3.w;
    float* outp = g_agg + dst * 64 + lane * 4;
    atomicAdd(outp,     acc.x);
    atomicAdd(outp + 1, acc.y);
    atomicAdd(outp + 2, acc.z);
    atomicAdd(outp + 3, acc.w);
}

// ---------------- out = relu(agg/deg + x@root + b); zero agg for next layer ----------------
template <int CIN, int LAYER>
__global__ __launch_bounds__(256) void finalize_kernel(const float* __restrict__ xin,
                                                       const float* __restrict__ root,
                                                       const float* __restrict__ bias) {
    __shared__ __align__(16) float xs[CIN][68];
    __shared__ __align__(16) float ws[CIN * 64];
    const float* src = (LAYER == 0) ? xin : g_x1;
    float* dstbuf    = (LAYER == 0) ? g_x1 : g_x2;
    int n0 = blockIdx.x * 64;
    int t  = threadIdx.x;

    for (int idx = t; idx < 64 * CIN; idx += 256) {
        int nl = idx / CIN, i = idx % CIN;
        int n = n0 + nl;
        xs[i][nl] = (n < NN) ? src[n * CIN + i] : 0.f;
    }
    for (int idx = t; idx < CIN * 64; idx += 256)
        ws[idx] = root[idx];
    __syncthreads();

    int tx = t & 15, ty = t >> 4;
    float acc[4][4] = {};
#pragma unroll 8
    for (int i = 0; i < CIN; i++)
        mac16(acc, &xs[i][ty * 4], &ws[i * 64 + tx * 4]);

    int obase = tx * 4;
    float4 bv = *(const float4*)&bias[obase];
#pragma unroll
    for (int j = 0; j < 4; j++) {
        int n = n0 + ty * 4 + j;
        if (n < NN) {
            float inv = 1.f / fmaxf(g_deg[n], 1.f);
            float4 a = *(const float4*)&g_agg[n * 64 + obase];
            float4 v;
            v.x = fmaxf(acc[j][0] + a.x * inv + bv.x, 0.f);
            v.y = fmaxf(acc[j][1] + a.y * inv + bv.y, 0.f);
            v.z = fmaxf(acc[j][2] + a.z * inv + bv.z, 0.f);
            v.w = fmaxf(acc[j][3] + a.w * inv + bv.w, 0.f);
            *(float4*)&dstbuf[n * 64 + obase] = v;
            *(float4*)&g_agg[n * 64 + obase] = make_float4(0.f, 0.f, 0.f, 0.f);
        }
    }
}

// ---------------- out = [x | x1 | x2] @ fw + fb ----------------
__global__ __launch_bounds__(256) void final_kernel(const float* __restrict__ x,
                                                    const float* __restrict__ fw,
                                                    const float* __restrict__ fb,
                                                    float* __restrict__ out) {
    __shared__ __align__(16) float xs[64][68];
    __shared__ __align__(16) float ws[64 * 64];
    int n0 = blockIdx.x * 64;
    int t  = threadIdx.x;
    int tx = t & 15, ty = t >> 4;
    float acc[4][4] = {};

#pragma unroll 1
    for (int c = 0; c < 3; c++) {
        const float* srcp;
        int cin, roff;
        if (c == 0)      { srcp = x;    cin = 32; roff = 0;  }
        else if (c == 1) { srcp = g_x1; cin = 64; roff = 32; }
        else             { srcp = g_x2; cin = 64; roff = 96; }

        for (int idx = t; idx < 64 * cin; idx += 256) {
            int nl = idx / cin, i = idx % cin;
            int n = n0 + nl;
            xs[i][nl] = (n < NN) ? srcp[n * cin + i] : 0.f;
        }
        for (int idx = t; idx < cin * 64; idx += 256)
            ws[idx] = fw[roff * 64 + idx];
        __syncthreads();

#pragma unroll 8
        for (int i = 0; i < cin; i++)
            mac16(acc, &xs[i][ty * 4], &ws[i * 64 + tx * 4]);
        __syncthreads();
    }

    int obase = tx * 4;
    float4 bv = *(const float4*)&fb[obase];
#pragma unroll
    for (int j = 0; j < 4; j++) {
        int n = n0 + ty * 4 + j;
        if (n < NN) {
            float4 v = make_float4(acc[j][0] + bv.x, acc[j][1] + bv.y,
                                   acc[j][2] + bv.z, acc[j][3] + bv.w);
            *(float4*)&out[n * 64 + obase] = v;
        }
    }
}

// ---------------- launch ----------------
extern "C" void kernel_launch(void* const* d_in, const int* in_sizes, int n_in,
                              void* d_out, int out_size) {
    (void)in_sizes; (void)n_in; (void)out_size;
    const float* x     = (const float*)d_in[0];
    const void*  ei    = d_in[1];            // int64 OR int32 — detected at runtime
    const float* attr  = (const float*)d_in[2];
    const float* w0    = (const float*)d_in[3];
    const float* root0 = (const float*)d_in[4];
    const float* b0    = (const float*)d_in[5];
    const float* w1    = (const float*)d_in[6];
    const float* root1 = (const float*)d_in[7];
    const float* b1    = (const float*)d_in[8];
    const float* fw    = (const float*)d_in[9];
    const float* fb    = (const float*)d_in[10];
    float*       out   = (float*)d_out;

    const int nodeTiles = (NN + 63) / 64;   // 782

    detect_kernel<<<1, 32>>>(ei);
    zero_kernel<<<(NN * OUTC + 255) / 256, 256>>>();
    prep_kernel<<<(EE + 255) / 256, 256>>>(ei, attr);

    // layer 0
    transform_kernel<INC, 0><<<dim3(nodeTiles, KPROD), 256>>>(x, w0);
    gather_kernel<<<EE / 16, 256>>>();
    finalize_kernel<INC, 0><<<nodeTiles, 256>>>(x, root0, b0);

    // layer 1
    transform_kernel<OUTC, 1><<<dim3(nodeTiles, KPROD), 256>>>(nullptr, w1);
    gather_kernel<<<EE / 16, 256>>>();
    finalize_kernel<OUTC, 1><<<nodeTiles, 256>>>(nullptr, root1, b1);

    // final concat linear
    final_kernel<<<nodeTiles, 256>>>(x, fw, fb, out);
}

// round 15
// speedup vs baseline: 1.1520x; 1.1520x over previous
#include <cuda_runtime.h>

#define NN 50000
#define EE 800000
#define INC 32
#define OUTC 64
#define KPROD 25
#define TK 16   // k-chunk for transform

// ---------------- device scratch (no allocation allowed) ----------------
__device__ __align__(16) int    g_src[EE];
__device__ __align__(16) int    g_dst[EE];
__device__ __align__(16) float4 g_basis[EE];
__device__ __align__(16) uchar4 g_widx[EE];
__device__ __align__(16) float  g_y[(size_t)NN * KPROD * OUTC];   // 320 MB
__device__ __align__(16) float  g_agg[NN * OUTC];
__device__ __align__(16) float  g_deg[NN];
__device__ __align__(16) float  g_x1[NN * OUTC];
__device__ __align__(16) float  g_x2[NN * OUTC];
__device__ int g_is64;   // 1 if edge_index buffer is true int64, 0 if int32

// ---------------- detect edge_index dtype (runs every replay; deterministic) ----------------
__global__ void detect_kernel(const void* ei) {
    if (threadIdx.x == 0 && blockIdx.x == 0) {
        const long long* p64 = (const long long*)ei;
        int ok64 = 1;
        for (int i = 0; i < 64; i++) {
            long long v = p64[i];
            if (v < 0 || v >= NN) { ok64 = 0; break; }
        }
        g_is64 = ok64;
    }
}

// ---------------- zero agg + deg (start of each replay) ----------------
__global__ void zero_kernel() {
    int i = blockIdx.x * blockDim.x + threadIdx.x;
    if (i < NN * OUTC) g_agg[i] = 0.f;
    if (i < NN)        g_deg[i] = 0.f;
}

// ---------------- per-edge basis / widx / src / dst / deg ----------------
__global__ __launch_bounds__(256) void prep_kernel(const void* __restrict__ ei,
                                                   const float* __restrict__ attr) {
    int e = blockIdx.x * 256 + threadIdx.x;
    if (e >= EE) return;
    int s, d;
    if (g_is64) {
        const long long* p = (const long long*)ei;
        s = (int)p[e];
        d = (int)p[EE + e];
    } else {
        const int* p = (const int*)ei;
        s = p[e];
        d = p[EE + e];
    }
    // defensive clamp: any residual garbage becomes a rel_err signal, not a trap
    s = min(max(s, 0), NN - 1);
    d = min(max(d, 0), NN - 1);
    g_src[e] = s;
    g_dst[e] = d;
    atomicAdd(&g_deg[d], 1.f);

    float v0 = attr[2 * e]     * 4.f;
    float v1 = attr[2 * e + 1] * 4.f;
    float fl0 = floorf(v0), fl1 = floorf(v1);
    int   b0 = (int)fl0,    b1 = (int)fl1;
    float f0 = v0 - fl0,    f1 = v1 - fl1;
    float g0 = 1.f - f0,    g1 = 1.f - f1;

    float4 bas = make_float4(g0 * g1, f0 * g1, g0 * f1, f0 * f1);
    int k00 = min(max(b0, 0), 4), k01 = min(max(b0 + 1, 0), 4);
    int k10 = min(max(b1, 0), 4), k11 = min(max(b1 + 1, 0), 4);
    uchar4 wi;
    wi.x = (unsigned char)(k00 + 5 * k10);
    wi.y = (unsigned char)(k01 + 5 * k10);
    wi.z = (unsigned char)(k00 + 5 * k11);
    wi.w = (unsigned char)(k01 + 5 * k11);
    g_basis[e] = bas;
    g_widx[e]  = wi;
}

// ---------------- y[n,k,:] = x[n,:] @ w[k]   256-node x 64-out tile, 8x8 microtile ----------------
// Per k-step: 4 LDS.128 -> 64 FFMA (0.75 B smem / FFMA vs 2.0 before).
template <int CIN, int LAYER>
__global__ __launch_bounds__(256) void transform_kernel(const float* __restrict__ xin,
                                                        const float* __restrict__ w) {
    __shared__ __align__(16) float xs[TK][260];   // transposed x; stride 260 keeps rows 16B-aligned
    __shared__ __align__(16) float ws[TK * 64];
    const float* src = (LAYER == 0) ? xin : g_x1;
    int k  = blockIdx.y;
    int n0 = blockIdx.x * 256;
    int t  = threadIdx.x;
    int tx = t & 7;        // out group: cols tx*8 .. tx*8+7
    int ty = t >> 3;       // node group: rows ty*8 .. ty*8+7

    float acc[8][8];
#pragma unroll
    for (int j = 0; j < 8; j++)
#pragma unroll
        for (int c = 0; c < 8; c++) acc[j][c] = 0.f;

    for (int kc = 0; kc < CIN; kc += TK) {
        // xs load: 256 nodes x TK cols, transposed into xs[i][node]
#pragma unroll
        for (int jj = 0; jj < 4; jj++) {
            int idx  = t + 256 * jj;       // float4 index, 0..1023
            int node = idx >> 2;
            int iv   = idx & 3;
            int n = n0 + node;
            float4 v = (n < NN) ? *(const float4*)&src[n * CIN + kc + iv * 4]
                                : make_float4(0.f, 0.f, 0.f, 0.f);
            xs[iv * 4 + 0][node] = v.x;
            xs[iv * 4 + 1][node] = v.y;
            xs[iv * 4 + 2][node] = v.z;
            xs[iv * 4 + 3][node] = v.w;
        }
        // ws load: TK*64 = 1024 contiguous floats = 256 float4
        ((float4*)ws)[t] = ((const float4*)&w[(k * CIN + kc) * 64])[t];
        __syncthreads();

#pragma unroll
        for (int i = 0; i < TK; i++) {
            float4 xa = *(const float4*)&xs[i][ty * 8];
            float4 xb = *(const float4*)&xs[i][ty * 8 + 4];
            float4 wa = *(const float4*)&ws[i * 64 + tx * 8];
            float4 wb = *(const float4*)&ws[i * 64 + tx * 8 + 4];
            float xv[8] = {xa.x, xa.y, xa.z, xa.w, xb.x, xb.y, xb.z, xb.w};
            float wv[8] = {wa.x, wa.y, wa.z, wa.w, wb.x, wb.y, wb.z, wb.w};
#pragma unroll
            for (int j = 0; j < 8; j++)
#pragma unroll
                for (int c = 0; c < 8; c++)
                    acc[j][c] += xv[j] * wv[c];
        }
        __syncthreads();
    }

#pragma unroll
    for (int j = 0; j < 8; j++) {
        int n = n0 + ty * 8 + j;
        if (n < NN) {
            float* dst = &g_y[((size_t)n * KPROD + k) * 64 + tx * 8];
            *(float4*)dst       = make_float4(acc[j][0], acc[j][1], acc[j][2], acc[j][3]);
            *(float4*)(dst + 4) = make_float4(acc[j][4], acc[j][5], acc[j][6], acc[j][7]);
        }
    }
}

// ---------------- per-edge gather of 4 y-rows, scatter-add to agg ----------------
__global__ __launch_bounds__(256) void gather_kernel() {
    int gtid = blockIdx.x * 256 + threadIdx.x;
    int e    = gtid >> 4;          // edge index
    int lane = gtid & 15;          // 16 lanes cover 64 floats as float4
    if (e >= EE) return;
    int src = g_src[e];
    int dst = g_dst[e];
    float4 bas = g_basis[e];
    uchar4 wi  = g_widx[e];
    const float4* __restrict__ base = (const float4*)(g_y + (size_t)src * (KPROD * 64));
    float4 v0 = __ldg(&base[wi.x * 16 + lane]);
    float4 v1 = __ldg(&base[wi.y * 16 + lane]);
    float4 v2 = __ldg(&base[wi.z * 16 + lane]);
    float4 v3 = __ldg(&base[wi.w * 16 + lane]);
    float4 acc;
    acc.x = bas.x * v0.x + bas.y * v1.x + bas.z * v2.x + bas.w * v3.x;
    acc.y = bas.x * v0.y + bas.y * v1.y + bas.z * v2.y + bas.w * v3.y;
    acc.z = bas.x * v0.z + bas.y * v1.z + bas.z * v2.z + bas.w * v3.z;
    acc.w = bas.x * v0.w + bas.y * v1.w + bas.z * v2.w + bas.w * v3.w;
    float* outp = g_agg + dst * 64 + lane * 4;
    atomicAdd(outp,     acc.x);
    atomicAdd(outp + 1, acc.y);
    atomicAdd(outp + 2, acc.z);
    atomicAdd(outp + 3, acc.w);
}

// ---------------- 4x4 microtile MAC (small GEMMs) ----------------
__device__ __forceinline__ void mac16(float acc[4][4], const float* xsrow, const float* wsrow) {
    float4 xv = *(const float4*)xsrow;
    float4 wv = *(const float4*)wsrow;
    acc[0][0] += xv.x * wv.x; acc[0][1] += xv.x * wv.y; acc[0][2] += xv.x * wv.z; acc[0][3] += xv.x * wv.w;
    acc[1][0] += xv.y * wv.x; acc[1][1] += xv.y * wv.y; acc[1][2] += xv.y * wv.z; acc[1][3] += xv.y * wv.w;
    acc[2][0] += xv.z * wv.x; acc[2][1] += xv.z * wv.y; acc[2][2] += xv.z * wv.z; acc[2][3] += xv.z * wv.w;
    acc[3][0] += xv.w * wv.x; acc[3][1] += xv.w * wv.y; acc[3][2] += xv.w * wv.z; acc[3][3] += xv.w * wv.w;
}

// ---------------- out = relu(agg/deg + x@root + b); zero agg for next layer ----------------
template <int CIN, int LAYER>
__global__ __launch_bounds__(256) void finalize_kernel(const float* __restrict__ xin,
                                                       const float* __restrict__ root,
                                                       const float* __restrict__ bias) {
    __shared__ __align__(16) float xs[CIN][68];
    __shared__ __align__(16) float ws[CIN * 64];
    const float* src = (LAYER == 0) ? xin : g_x1;
    float* dstbuf    = (LAYER == 0) ? g_x1 : g_x2;
    int n0 = blockIdx.x * 64;
    int t  = threadIdx.x;

    for (int idx = t; idx < 64 * CIN; idx += 256) {
        int nl = idx / CIN, i = idx % CIN;
        int n = n0 + nl;
        xs[i][nl] = (n < NN) ? src[n * CIN + i] : 0.f;
    }
    for (int idx = t; idx < CIN * 64; idx += 256)
        ws[idx] = root[idx];
    __syncthreads();

    int tx = t & 15, ty = t >> 4;
    float acc[4][4] = {};
#pragma unroll 8
    for (int i = 0; i < CIN; i++)
        mac16(acc, &xs[i][ty * 4], &ws[i * 64 + tx * 4]);

    int obase = tx * 4;
    float4 bv = *(const float4*)&bias[obase];
#pragma unroll
    for (int j = 0; j < 4; j++) {
        int n = n0 + ty * 4 + j;
        if (n < NN) {
            float inv = 1.f / fmaxf(g_deg[n], 1.f);
            float4 a = *(const float4*)&g_agg[n * 64 + obase];
            float4 v;
            v.x = fmaxf(acc[j][0] + a.x * inv + bv.x, 0.f);
            v.y = fmaxf(acc[j][1] + a.y * inv + bv.y, 0.f);
            v.z = fmaxf(acc[j][2] + a.z * inv + bv.z, 0.f);
            v.w = fmaxf(acc[j][3] + a.w * inv + bv.w, 0.f);
            *(float4*)&dstbuf[n * 64 + obase] = v;
            *(float4*)&g_agg[n * 64 + obase] = make_float4(0.f, 0.f, 0.f, 0.f);
        }
    }
}

// ---------------- out = [x | x1 | x2] @ fw + fb ----------------
__global__ __launch_bounds__(256) void final_kernel(const float* __restrict__ x,
                                                    const float* __restrict__ fw,
                                                    const float* __restrict__ fb,
                                                    float* __restrict__ out) {
    __shared__ __align__(16) float xs[64][68];
    __shared__ __align__(16) float ws[64 * 64];
    int n0 = blockIdx.x * 64;
    int t  = threadIdx.x;
    int tx = t & 15, ty = t >> 4;
    float acc[4][4] = {};

#pragma unroll 1
    for (int c = 0; c < 3; c++) {
        const float* srcp;
        int cin, roff;
        if (c == 0)      { srcp = x;    cin = 32; roff = 0;  }
        else if (c == 1) { srcp = g_x1; cin = 64; roff = 32; }
        else             { srcp = g_x2; cin = 64; roff = 96; }

        for (int idx = t; idx < 64 * cin; idx += 256) {
            int nl = idx / cin, i = idx % cin;
            int n = n0 + nl;
            xs[i][nl] = (n < NN) ? srcp[n * cin + i] : 0.f;
        }
        for (int idx = t; idx < cin * 64; idx += 256)
            ws[idx] = fw[roff * 64 + idx];
        __syncthreads();

#pragma unroll 8
        for (int i = 0; i < cin; i++)
            mac16(acc, &xs[i][ty * 4], &ws[i * 64 + tx * 4]);
        __syncthreads();
    }

    int obase = tx * 4;
    float4 bv = *(const float4*)&fb[obase];
#pragma unroll
    for (int j = 0; j < 4; j++) {
        int n = n0 + ty * 4 + j;
        if (n < NN) {
            float4 v = make_float4(acc[j][0] + bv.x, acc[j][1] + bv.y,
                                   acc[j][2] + bv.z, acc[j][3] + bv.w);
            *(float4*)&out[n * 64 + obase] = v;
        }
    }
}

// ---------------- launch ----------------
extern "C" void kernel_launch(void* const* d_in, const int* in_sizes, int n_in,
                              void* d_out, int out_size) {
    (void)in_sizes; (void)n_in; (void)out_size;
    const float* x     = (const float*)d_in[0];
    const void*  ei    = d_in[1];            // int64 OR int32 — detected at runtime
    const float* attr  = (const float*)d_in[2];
    const float* w0    = (const float*)d_in[3];
    const float* root0 = (const float*)d_in[4];
    const float* b0    = (const float*)d_in[5];
    const float* w1    = (const float*)d_in[6];
    const float* root1 = (const float*)d_in[7];
    const float* b1    = (const float*)d_in[8];
    const float* fw    = (const float*)d_in[9];
    const float* fb    = (const float*)d_in[10];
    float*       out   = (float*)d_out;

    const int nodeTiles   = (NN + 63) / 64;    // 782 (small GEMMs)
    const int xformTiles  = (NN + 255) / 256;  // 196 (transform)

    detect_kernel<<<1, 32>>>(ei);
    zero_kernel<<<(NN * OUTC + 255) / 256, 256>>>();
    prep_kernel<<<(EE + 255) / 256, 256>>>(ei, attr);

    // layer 0
    transform_kernel<INC, 0><<<dim3(xformTiles, KPROD), 256>>>(x, w0);
    gather_kernel<<<EE / 16, 256>>>();
    finalize_kernel<INC, 0><<<nodeTiles, 256>>>(x, root0, b0);

    // layer 1
    transform_kernel<OUTC, 1><<<dim3(xformTiles, KPROD), 256>>>(nullptr, w1);
    gather_kernel<<<EE / 16, 256>>>();
    finalize_kernel<OUTC, 1><<<nodeTiles, 256>>>(nullptr, root1, b1);

    // final concat linear
    final_kernel<<<nodeTiles, 256>>>(x, fw, fb, out);
}

// round 16
// speedup vs baseline: 1.1660x; 1.0121x over previous
#include <cuda_runtime.h>

#define NN 50000
#define EE 800000
#define INC 32
#define OUTC 64
#define KPROD 25
#define TK 16   // k-chunk for transform

// ---------------- device scratch (no allocation allowed) ----------------
__device__ __align__(16) int    g_src[EE];
__device__ __align__(16) int    g_dst[EE];
__device__ __align__(16) float4 g_basis[EE];
__device__ __align__(16) uchar4 g_widx[EE];
__device__ __align__(16) float  g_y[(size_t)NN * KPROD * OUTC];   // 320 MB
__device__ __align__(16) float  g_agg[NN * OUTC];
__device__ __align__(16) float  g_deg[NN];
__device__ __align__(16) float  g_x1[NN * OUTC];
__device__ __align__(16) float  g_x2[NN * OUTC];
__device__ int g_is64;   // 1 if edge_index buffer is true int64, 0 if int32

// ---------------- detect edge_index dtype (runs every replay; deterministic) ----------------
__global__ void detect_kernel(const void* ei) {
    if (threadIdx.x == 0 && blockIdx.x == 0) {
        const long long* p64 = (const long long*)ei;
        int ok64 = 1;
        for (int i = 0; i < 64; i++) {
            long long v = p64[i];
            if (v < 0 || v >= NN) { ok64 = 0; break; }
        }
        g_is64 = ok64;
    }
}

// ---------------- zero agg + deg (start of each replay) ----------------
__global__ void zero_kernel() {
    int i = blockIdx.x * blockDim.x + threadIdx.x;
    if (i < NN * OUTC) g_agg[i] = 0.f;
    if (i < NN)        g_deg[i] = 0.f;
}

// ---------------- per-edge basis / widx / src / dst / deg ----------------
__global__ __launch_bounds__(256) void prep_kernel(const void* __restrict__ ei,
                                                   const float* __restrict__ attr) {
    int e = blockIdx.x * 256 + threadIdx.x;
    if (e >= EE) return;
    int s, d;
    if (g_is64) {
        const long long* p = (const long long*)ei;
        s = (int)p[e];
        d = (int)p[EE + e];
    } else {
        const int* p = (const int*)ei;
        s = p[e];
        d = p[EE + e];
    }
    // defensive clamp: any residual garbage becomes a rel_err signal, not a trap
    s = min(max(s, 0), NN - 1);
    d = min(max(d, 0), NN - 1);
    g_src[e] = s;
    g_dst[e] = d;
    atomicAdd(&g_deg[d], 1.f);

    float v0 = attr[2 * e]     * 4.f;
    float v1 = attr[2 * e + 1] * 4.f;
    float fl0 = floorf(v0), fl1 = floorf(v1);
    int   b0 = (int)fl0,    b1 = (int)fl1;
    float f0 = v0 - fl0,    f1 = v1 - fl1;
    float g0 = 1.f - f0,    g1 = 1.f - f1;

    float4 bas = make_float4(g0 * g1, f0 * g1, g0 * f1, f0 * f1);
    int k00 = min(max(b0, 0), 4), k01 = min(max(b0 + 1, 0), 4);
    int k10 = min(max(b1, 0), 4), k11 = min(max(b1 + 1, 0), 4);
    uchar4 wi;
    wi.x = (unsigned char)(k00 + 5 * k10);
    wi.y = (unsigned char)(k01 + 5 * k10);
    wi.z = (unsigned char)(k00 + 5 * k11);
    wi.w = (unsigned char)(k01 + 5 * k11);
    g_basis[e] = bas;
    g_widx[e]  = wi;
}

// ---------------- packed f32x2 helpers ----------------
__device__ __forceinline__ unsigned long long pack_dup(float x) {
    unsigned long long r;
    asm("mov.b64 %0, {%1, %1};" : "=l"(r) : "r"(__float_as_int(x)));
    return r;
}
__device__ __forceinline__ void fma2(unsigned long long& acc, unsigned long long a, unsigned long long b) {
    asm("fma.rn.f32x2 %0, %1, %2, %0;" : "+l"(acc) : "l"(a), "l"(b));
}
__device__ __forceinline__ float2 unpack2(unsigned long long v) {
    int lo, hi;
    asm("mov.b64 {%0, %1}, %2;" : "=r"(lo), "=r"(hi) : "l"(v));
    return make_float2(__int_as_float(lo), __int_as_float(hi));
}

// ---------------- y[n,k,:] = x[n,:] @ w[k]   256-node x 64-out tile, 8x8 microtile ----------------
// Inner math via fma.rn.f32x2: 32 FFMA2 per i-step (halves fma-pipe time vs 64 FFMA).
template <int CIN, int LAYER>
__global__ __launch_bounds__(256) void transform_kernel(const float* __restrict__ xin,
                                                        const float* __restrict__ w) {
    __shared__ __align__(16) float xs[TK][260];   // transposed x; stride 260 keeps rows 16B-aligned
    __shared__ __align__(16) float ws[TK * 64];
    const float* src = (LAYER == 0) ? xin : g_x1;
    int k  = blockIdx.y;
    int n0 = blockIdx.x * 256;
    int t  = threadIdx.x;
    int tx = t & 7;        // out group: cols tx*8 .. tx*8+7 (4 f32x2 pairs)
    int ty = t >> 3;       // node group: rows ty*8 .. ty*8+7

    unsigned long long acc[8][4];
#pragma unroll
    for (int j = 0; j < 8; j++)
#pragma unroll
        for (int c = 0; c < 4; c++) acc[j][c] = 0ull;

    for (int kc = 0; kc < CIN; kc += TK) {
        // xs load: 256 nodes x TK cols, transposed into xs[i][node]
#pragma unroll
        for (int jj = 0; jj < 4; jj++) {
            int idx  = t + 256 * jj;       // float4 index, 0..1023
            int node = idx >> 2;
            int iv   = idx & 3;
            int n = n0 + node;
            float4 v = (n < NN) ? *(const float4*)&src[n * CIN + kc + iv * 4]
                                : make_float4(0.f, 0.f, 0.f, 0.f);
            xs[iv * 4 + 0][node] = v.x;
            xs[iv * 4 + 1][node] = v.y;
            xs[iv * 4 + 2][node] = v.z;
            xs[iv * 4 + 3][node] = v.w;
        }
        // ws load: TK*64 = 1024 contiguous floats = 256 float4
        ((float4*)ws)[t] = ((const float4*)&w[(k * CIN + kc) * 64])[t];
        __syncthreads();

#pragma unroll
        for (int i = 0; i < TK; i++) {
            float4 xa = *(const float4*)&xs[i][ty * 8];
            float4 xb = *(const float4*)&xs[i][ty * 8 + 4];
            // same 16B reinterpreted as packed f32x2 pairs {w0,w1},{w2,w3},...
            ulonglong2 wa = *(const ulonglong2*)&ws[i * 64 + tx * 8];
            ulonglong2 wb = *(const ulonglong2*)&ws[i * 64 + tx * 8 + 4];
            unsigned long long wp[4] = {wa.x, wa.y, wb.x, wb.y};
            float xv[8] = {xa.x, xa.y, xa.z, xa.w, xb.x, xb.y, xb.z, xb.w};
#pragma unroll
            for (int j = 0; j < 8; j++) {
                unsigned long long xp = pack_dup(xv[j]);
#pragma unroll
                for (int c = 0; c < 4; c++)
                    fma2(acc[j][c], xp, wp[c]);
            }
        }
        __syncthreads();
    }

#pragma unroll
    for (int j = 0; j < 8; j++) {
        int n = n0 + ty * 8 + j;
        if (n < NN) {
            float2 p0 = unpack2(acc[j][0]);
            float2 p1 = unpack2(acc[j][1]);
            float2 p2 = unpack2(acc[j][2]);
            float2 p3 = unpack2(acc[j][3]);
            float* dst = &g_y[((size_t)n * KPROD + k) * 64 + tx * 8];
            *(float4*)dst       = make_float4(p0.x, p0.y, p1.x, p1.y);
            *(float4*)(dst + 4) = make_float4(p2.x, p2.y, p3.x, p3.y);
        }
    }
}

// ---------------- per-edge gather of 4 y-rows, scatter-add to agg ----------------
__global__ __launch_bounds__(256) void gather_kernel() {
    int gtid = blockIdx.x * 256 + threadIdx.x;
    int e    = gtid >> 4;          // edge index
    int lane = gtid & 15;          // 16 lanes cover 64 floats as float4
    if (e >= EE) return;
    int src = g_src[e];
    int dst = g_dst[e];
    float4 bas = g_basis[e];
    uchar4 wi  = g_widx[e];
    const float4* __restrict__ base = (const float4*)(g_y + (size_t)src * (KPROD * 64));
    float4 v0 = __ldg(&base[wi.x * 16 + lane]);
    float4 v1 = __ldg(&base[wi.y * 16 + lane]);
    float4 v2 = __ldg(&base[wi.z * 16 + lane]);
    float4 v3 = __ldg(&base[wi.w * 16 + lane]);
    float4 acc;
    acc.x = bas.x * v0.x + bas.y * v1.x + bas.z * v2.x + bas.w * v3.x;
    acc.y = bas.x * v0.y + bas.y * v1.y + bas.z * v2.y + bas.w * v3.y;
    acc.z = bas.x * v0.z + bas.y * v1.z + bas.z * v2.z + bas.w * v3.z;
    acc.w = bas.x * v0.w + bas.y * v1.w + bas.z * v2.w + bas.w * v3.w;
    float* outp = g_agg + dst * 64 + lane * 4;
    atomicAdd(outp,     acc.x);
    atomicAdd(outp + 1, acc.y);
    atomicAdd(outp + 2, acc.z);
    atomicAdd(outp + 3, acc.w);
}

// ---------------- 4x4 microtile MAC (small GEMMs) ----------------
__device__ __forceinline__ void mac16(float acc[4][4], const float* xsrow, const float* wsrow) {
    float4 xv = *(const float4*)xsrow;
    float4 wv = *(const float4*)wsrow;
    acc[0][0] += xv.x * wv.x; acc[0][1] += xv.x * wv.y; acc[0][2] += xv.x * wv.z; acc[0][3] += xv.x * wv.w;
    acc[1][0] += xv.y * wv.x; acc[1][1] += xv.y * wv.y; acc[1][2] += xv.y * wv.z; acc[1][3] += xv.y * wv.w;
    acc[2][0] += xv.z * wv.x; acc[2][1] += xv.z * wv.y; acc[2][2] += xv.z * wv.z; acc[2][3] += xv.z * wv.w;
    acc[3][0] += xv.w * wv.x; acc[3][1] += xv.w * wv.y; acc[3][2] += xv.w * wv.z; acc[3][3] += xv.w * wv.w;
}

// ---------------- out = relu(agg/deg + x@root + b); zero agg for next layer ----------------
template <int CIN, int LAYER>
__global__ __launch_bounds__(256) void finalize_kernel(const float* __restrict__ xin,
                                                       const float* __restrict__ root,
                                                       const float* __restrict__ bias) {
    __shared__ __align__(16) float xs[CIN][68];
    __shared__ __align__(16) float ws[CIN * 64];
    const float* src = (LAYER == 0) ? xin : g_x1;
    float* dstbuf    = (LAYER == 0) ? g_x1 : g_x2;
    int n0 = blockIdx.x * 64;
    int t  = threadIdx.x;

    for (int idx = t; idx < 64 * CIN; idx += 256) {
        int nl = idx / CIN, i = idx % CIN;
        int n = n0 + nl;
        xs[i][nl] = (n < NN) ? src[n * CIN + i] : 0.f;
    }
    for (int idx = t; idx < CIN * 64; idx += 256)
        ws[idx] = root[idx];
    __syncthreads();

    int tx = t & 15, ty = t >> 4;
    float acc[4][4] = {};
#pragma unroll 8
    for (int i = 0; i < CIN; i++)
        mac16(acc, &xs[i][ty * 4], &ws[i * 64 + tx * 4]);

    int obase = tx * 4;
    float4 bv = *(const float4*)&bias[obase];
#pragma unroll
    for (int j = 0; j < 4; j++) {
        int n = n0 + ty * 4 + j;
        if (n < NN) {
            float inv = 1.f / fmaxf(g_deg[n], 1.f);
            float4 a = *(const float4*)&g_agg[n * 64 + obase];
            float4 v;
            v.x = fmaxf(acc[j][0] + a.x * inv + bv.x, 0.f);
            v.y = fmaxf(acc[j][1] + a.y * inv + bv.y, 0.f);
            v.z = fmaxf(acc[j][2] + a.z * inv + bv.z, 0.f);
            v.w = fmaxf(acc[j][3] + a.w * inv + bv.w, 0.f);
            *(float4*)&dstbuf[n * 64 + obase] = v;
            *(float4*)&g_agg[n * 64 + obase] = make_float4(0.f, 0.f, 0.f, 0.f);
        }
    }
}

// ---------------- out = [x | x1 | x2] @ fw + fb ----------------
__global__ __launch_bounds__(256) void final_kernel(const float* __restrict__ x,
                                                    const float* __restrict__ fw,
                                                    const float* __restrict__ fb,
                                                    float* __restrict__ out) {
    __shared__ __align__(16) float xs[64][68];
    __shared__ __align__(16) float ws[64 * 64];
    int n0 = blockIdx.x * 64;
    int t  = threadIdx.x;
    int tx = t & 15, ty = t >> 4;
    float acc[4][4] = {};

#pragma unroll 1
    for (int c = 0; c < 3; c++) {
        const float* srcp;
        int cin, roff;
        if (c == 0)      { srcp = x;    cin = 32; roff = 0;  }
        else if (c == 1) { srcp = g_x1; cin = 64; roff = 32; }
        else             { srcp = g_x2; cin = 64; roff = 96; }

        for (int idx = t; idx < 64 * cin; idx += 256) {
            int nl = idx / cin, i = idx % cin;
            int n = n0 + nl;
            xs[i][nl] = (n < NN) ? srcp[n * cin + i] : 0.f;
        }
        for (int idx = t; idx < cin * 64; idx += 256)
            ws[idx] = fw[roff * 64 + idx];
        __syncthreads();

#pragma unroll 8
        for (int i = 0; i < cin; i++)
            mac16(acc, &xs[i][ty * 4], &ws[i * 64 + tx * 4]);
        __syncthreads();
    }

    int obase = tx * 4;
    float4 bv = *(const float4*)&fb[obase];
#pragma unroll
    for (int j = 0; j < 4; j++) {
        int n = n0 + ty * 4 + j;
        if (n < NN) {
            float4 v = make_float4(acc[j][0] + bv.x, acc[j][1] + bv.y,
                                   acc[j][2] + bv.z, acc[j][3] + bv.w);
            *(float4*)&out[n * 64 + obase] = v;
        }
    }
}

// ---------------- launch ----------------
extern "C" void kernel_launch(void* const* d_in, const int* in_sizes, int n_in,
                              void* d_out, int out_size) {
    (void)in_sizes; (void)n_in; (void)out_size;
    const float* x     = (const float*)d_in[0];
    const void*  ei    = d_in[1];            // int64 OR int32 — detected at runtime
    const float* attr  = (const float*)d_in[2];
    const float* w0    = (const float*)d_in[3];
    const float* root0 = (const float*)d_in[4];
    const float* b0    = (const float*)d_in[5];
    const float* w1    = (const float*)d_in[6];
    const float* root1 = (const float*)d_in[7];
    const float* b1    = (const float*)d_in[8];
    const float* fw    = (const float*)d_in[9];
    const float* fb    = (const float*)d_in[10];
    float*       out   = (float*)d_out;

    const int nodeTiles   = (NN + 63) / 64;    // 782 (small GEMMs)
    const int xformTiles  = (NN + 255) / 256;  // 196 (transform)

    detect_kernel<<<1, 32>>>(ei);
    zero_kernel<<<(NN * OUTC + 255) / 256, 256>>>();
    prep_kernel<<<(EE + 255) / 256, 256>>>(ei, attr);

    // layer 0
    transform_kernel<INC, 0><<<dim3(xformTiles, KPROD), 256>>>(x, w0);
    gather_kernel<<<EE / 16, 256>>>();
    finalize_kernel<INC, 0><<<nodeTiles, 256>>>(x, root0, b0);

    // layer 1
    transform_kernel<OUTC, 1><<<dim3(xformTiles, KPROD), 256>>>(nullptr, w1);
    gather_kernel<<<EE / 16, 256>>>();
    finalize_kernel<OUTC, 1><<<nodeTiles, 256>>>(nullptr, root1, b1);

    // final concat linear
    final_kernel<<<nodeTiles, 256>>>(x, fw, fb, out);
}